// round 2
// baseline (speedup 1.0000x reference)
#include <cuda_runtime.h>
#include <cstdint>

// Problem constants
#define N_TOKENS 131072
#define EMBED    64
#define NCODES   1024

// Main kernel tiling
#define TILE_T   128
#define TILE_K   64
#define NTHREADS 256
#define E_STRIDE 68   // padded code-tile row stride (floats), 16B-aligned rows

#define LOSS_TOK_PER_BLK 64
#define NBLK_LOSS (N_TOKENS / LOSS_TOK_PER_BLK)   // 2048

// Scratch (allocation-free: __device__ globals)
__device__ float  g_esq[NCODES];
__device__ int    g_hist[NCODES];
__device__ double g_partial[NBLK_LOSS];

// ---- f32x2 helpers (bitwise-identical to scalar fp32 FFMA, 2x throughput) ----
#define PACKDUP(dst, f) \
    asm("mov.b64 %0, {%1, %1};" : "=l"(dst) : "r"(__float_as_uint(f)))
#define UNPACK2(lo, hi, v) \
    asm("mov.b64 {%0, %1}, %2;" : "=f"(lo), "=f"(hi) : "l"(v))
#define FMA2(d, a, b, c) \
    asm("fma.rn.f32x2 %0, %1, %2, %3;" : "=l"(d) : "l"(a), "l"(b), "l"(c))

// -------------------------------------------------------------------------
// Kernel 0: e_sq per code + zero histogram (re-run every replay for determinism)
// -------------------------------------------------------------------------
__global__ void vq_prep(const float* __restrict__ cb)
{
    int k = blockIdx.x * blockDim.x + threadIdx.x;
    if (k < NCODES) {
        const float* r = cb + (size_t)k * EMBED;
        float s = 0.f;
        #pragma unroll
        for (int d = 0; d < EMBED; ++d) s += r[d] * r[d];
        g_esq[k]  = s;
        g_hist[k] = 0;
    }
}

// -------------------------------------------------------------------------
// Kernel 1: fused distance + argmin.
//   score_k = (z_sq - 2*dot_k) + e_sq_k   (replicates reference fp32 rounding)
//   argmin with first-index tie-break (strict < scan, idx tie-break on merge)
// -------------------------------------------------------------------------
extern __shared__ float s_dyn[];

__global__ void __launch_bounds__(NTHREADS, 2)
vq_argmin(const float* __restrict__ z, const float* __restrict__ cb,
          float* __restrict__ out)
{
    float* sz  = s_dyn;                    // [64][128]  z tile, transposed
    float* se  = sz + EMBED * TILE_T;      // [64][68]   code tile, transposed
    float* szq = se + EMBED * E_STRIDE;    // [128]      z_sq per token

    const int tid   = threadIdx.x;
    const int tbase = blockIdx.x * TILE_T;

    // Load z tile transposed: sz[d][t] = z[tbase+t][d]
    for (int i = tid; i < EMBED * TILE_T; i += NTHREADS) {
        int t = i & (TILE_T - 1);
        int d = i >> 7;
        sz[d * TILE_T + t] = z[(size_t)(tbase + t) * EMBED + d];
    }
    __syncthreads();

    if (tid < TILE_T) {
        float s = 0.f;
        for (int d = 0; d < EMBED; ++d) {
            float v = sz[d * TILE_T + tid];
            s += v * v;
        }
        szq[tid] = s;
    }
    __syncthreads();

    const int t0 = (tid >> 3) * 4;      // 4 tokens per thread
    const int c0 = (tid & 7) * 8;       // 8 codes per thread (as 4 pairs)

    float zqr[4];
    #pragma unroll
    for (int i = 0; i < 4; ++i) zqr[i] = szq[t0 + i];

    float best[4];
    int   bidx[4];
    #pragma unroll
    for (int i = 0; i < 4; ++i) { best[i] = 3.4e38f; bidx[i] = 0; }

    for (int kt = 0; kt < NCODES / TILE_K; ++kt) {
        const int kb = kt * TILE_K;

        // Load code tile transposed: se[d][c] = cb[kb+c][d]  (coalesced gmem)
        for (int i = tid; i < TILE_K * EMBED; i += NTHREADS) {
            int d = i & 63;
            int c = i >> 6;
            se[d * E_STRIDE + c] = cb[(size_t)(kb + c) * EMBED + d];
        }
        __syncthreads();

        unsigned long long acc[4][4];   // [token][code-pair], f32x2 accumulators
        #pragma unroll
        for (int i = 0; i < 4; ++i)
            #pragma unroll
            for (int p = 0; p < 4; ++p) acc[i][p] = 0ULL;

        #pragma unroll 8
        for (int d = 0; d < EMBED; ++d) {
            float4 zv = *(const float4*)(sz + d * TILE_T + t0);
            ulonglong2 eA = *(const ulonglong2*)(se + d * E_STRIDE + c0);
            ulonglong2 eB = *(const ulonglong2*)(se + d * E_STRIDE + c0 + 4);

            unsigned long long zp0, zp1, zp2, zp3;
            PACKDUP(zp0, zv.x);
            PACKDUP(zp1, zv.y);
            PACKDUP(zp2, zv.z);
            PACKDUP(zp3, zv.w);

            FMA2(acc[0][0], zp0, eA.x, acc[0][0]);
            FMA2(acc[0][1], zp0, eA.y, acc[0][1]);
            FMA2(acc[0][2], zp0, eB.x, acc[0][2]);
            FMA2(acc[0][3], zp0, eB.y, acc[0][3]);
            FMA2(acc[1][0], zp1, eA.x, acc[1][0]);
            FMA2(acc[1][1], zp1, eA.y, acc[1][1]);
            FMA2(acc[1][2], zp1, eB.x, acc[1][2]);
            FMA2(acc[1][3], zp1, eB.y, acc[1][3]);
            FMA2(acc[2][0], zp2, eA.x, acc[2][0]);
            FMA2(acc[2][1], zp2, eA.y, acc[2][1]);
            FMA2(acc[2][2], zp2, eB.x, acc[2][2]);
            FMA2(acc[2][3], zp2, eB.y, acc[2][3]);
            FMA2(acc[3][0], zp3, eA.x, acc[3][0]);
            FMA2(acc[3][1], zp3, eA.y, acc[3][1]);
            FMA2(acc[3][2], zp3, eB.x, acc[3][2]);
            FMA2(acc[3][3], zp3, eB.y, acc[3][3]);
        }

        // Epilogue: score + running argmin (codes scanned in ascending k)
        #pragma unroll
        for (int i = 0; i < 4; ++i) {
            float zq = zqr[i];
            #pragma unroll
            for (int p = 0; p < 4; ++p) {
                float lo, hi;
                UNPACK2(lo, hi, acc[i][p]);
                int k0 = kb + c0 + 2 * p;
                float t1 = fmaf(-2.f, lo, zq);   // RN(zq - 2*dot), 2*dot exact
                float s0 = t1 + g_esq[k0];
                if (s0 < best[i]) { best[i] = s0; bidx[i] = k0; }
                float t2 = fmaf(-2.f, hi, zq);
                float s1 = t2 + g_esq[k0 + 1];
                if (s1 < best[i]) { best[i] = s1; bidx[i] = k0 + 1; }
            }
        }
        __syncthreads();
    }

    // Reduce across the 8 code-column lanes; tie -> smaller index (= first occurrence)
    #pragma unroll
    for (int i = 0; i < 4; ++i) {
        float b = best[i];
        int   x = bidx[i];
        #pragma unroll
        for (int off = 4; off; off >>= 1) {
            float b2 = __shfl_down_sync(0xffffffffu, b, off);
            int   x2 = __shfl_down_sync(0xffffffffu, x, off);
            if (b2 < b || (b2 == b && x2 < x)) { b = b2; x = x2; }
        }
        if ((tid & 7) == 0)
            out[(size_t)N_TOKENS * EMBED + tbase + t0 + i] = (float)x;
    }
}

// -------------------------------------------------------------------------
// Kernel 2: gather z_q, write straight-through output, MSE partial sums,
//           histogram. Deterministic per-block double reduction.
// -------------------------------------------------------------------------
__global__ void __launch_bounds__(256)
vq_loss(const float* __restrict__ z, const float* __restrict__ cb,
        float* __restrict__ out)
{
    __shared__ double sred[256];
    const int tid   = threadIdx.x;
    const int token = blockIdx.x * LOSS_TOK_PER_BLK + (tid >> 2);
    const int part  = tid & 3;

    const int idx = (int)out[(size_t)N_TOKENS * EMBED + token];

    const float* cp = cb  + (size_t)idx   * EMBED + part * 16;
    const float* zp = z   + (size_t)token * EMBED + part * 16;
    float*       op = out + (size_t)token * EMBED + part * 16;

    double acc = 0.0;
    #pragma unroll
    for (int q = 0; q < 4; ++q) {
        float4 e  = *(const float4*)(cp + q * 4);
        float4 zv = *(const float4*)(zp + q * 4);
        float dx = e.x - zv.x, dy = e.y - zv.y, dz = e.z - zv.z, dw = e.w - zv.w;
        float4 st = make_float4(zv.x + dx, zv.y + dy, zv.z + dz, zv.w + dw);
        *(float4*)(op + q * 4) = st;
        acc += (double)(dx * dx) + (double)(dy * dy)
             + (double)(dz * dz) + (double)(dw * dw);
    }

    sred[tid] = acc;
    __syncthreads();
    #pragma unroll
    for (int off = 128; off; off >>= 1) {
        if (tid < off) sred[tid] += sred[tid + off];
        __syncthreads();
    }
    if (tid == 0) g_partial[blockIdx.x] = sred[0];

    if (part == 0) atomicAdd(&g_hist[idx], 1);
}

// -------------------------------------------------------------------------
// Kernel 3: finalize scalars
// -------------------------------------------------------------------------
__global__ void __launch_bounds__(1024)
vq_final(float* __restrict__ out)
{
    __shared__ double sred[1024];
    __shared__ double s_loss;
    const int tid = threadIdx.x;

    sred[tid] = g_partial[tid] + g_partial[tid + 1024];
    __syncthreads();
    #pragma unroll
    for (int off = 512; off; off >>= 1) {
        if (tid < off) sred[tid] += sred[tid + off];
        __syncthreads();
    }
    if (tid == 0) s_loss = sred[0];
    __syncthreads();

    // entropy terms: p = c/n + 1e-10 (fp32, per reference), sum p*log(p)
    {
        float p = (float)g_hist[tid] / 131072.0f + 1e-10f;
        sred[tid] = (double)(p * logf(p));
    }
    __syncthreads();
    #pragma unroll
    for (int off = 512; off; off >>= 1) {
        if (tid < off) sred[tid] += sred[tid + off];
        __syncthreads();
    }

    if (tid == 0) {
        const size_t base = (size_t)N_TOKENS * EMBED + N_TOKENS;
        float cl      = (float)(s_loss / (double)((size_t)N_TOKENS * EMBED));
        float commit  = 0.25f * cl;
        float entropy = (float)(-sred[0]);
        float eloss   = -0.1f * (entropy / 6.9314718055994531f);
        float perp    = expf(entropy);
        out[base + 0] = cl;
        out[base + 1] = commit;
        out[base + 2] = eloss;
        out[base + 3] = perp;
    }
}

// -------------------------------------------------------------------------
extern "C" void kernel_launch(void* const* d_in, const int* in_sizes, int n_in,
                              void* d_out, int out_size)
{
    const float* z  = (const float*)d_in[0];   // z_e      [131072, 64]
    const float* cb = (const float*)d_in[1];   // codebook [1024, 64]
    float* out = (float*)d_out;

    const int smem_bytes = (EMBED * TILE_T + EMBED * E_STRIDE + TILE_T) * 4; // 50688
    static bool attr_set = false;
    if (!attr_set) {
        cudaFuncSetAttribute(vq_argmin,
                             cudaFuncAttributeMaxDynamicSharedMemorySize,
                             smem_bytes);
        attr_set = true;
    }

    vq_prep<<<(NCODES + 255) / 256, 256>>>(cb);
    vq_argmin<<<N_TOKENS / TILE_T, NTHREADS, smem_bytes>>>(z, cb, out);
    vq_loss<<<NBLK_LOSS, 256>>>(z, cb, out);
    vq_final<<<1, 1024>>>(out);
}

// round 3
// speedup vs baseline: 1.3415x; 1.3415x over previous
#include <cuda_runtime.h>
#include <cuda_fp16.h>
#include <cuda_bf16.h>
#include <cstdint>

#define N_TOKENS 131072
#define EMBED    64
#define NCODES   1024
#define TOK_BLK  64
#define NBLK     (N_TOKENS / TOK_BLK)
#define CBS      72                       // bf16 tile row stride (conflict-free)
#define SCS      1032                     // fp16 score row stride
#define CHUNK    256
#define CHELEM   (CHUNK * CBS)            // 18432 bf16 = 36864 B
#define QCAP     128

__device__ float  g_esq[NCODES];
__device__ float  g_emax;
__device__ int    g_hist[NCODES];
__device__ double g_partial[NBLK];
__device__ __nv_bfloat16 g_cbb[NCODES * CBS];

// smem byte offsets
#define O_SC   0
#define O_CB   132096
#define O_ZB   205824
#define O_EQ   215040
#define O_DL   219136
#define O_ZQ   219392
#define O_S4   219648
#define O_IX   220672
#define O_QC   220928
#define O_QU   220960
#define O_RD   225056
#define SMEMSZ 227104

__device__ __forceinline__ void cp16(void* d, const void* s) {
    unsigned a = (unsigned)__cvta_generic_to_shared(d);
    asm volatile("cp.async.cg.shared.global [%0], [%1], 16;" :: "r"(a), "l"(s));
}
__device__ __forceinline__ void mma16816(float* c, const unsigned* a, const unsigned* b) {
    asm volatile(
        "mma.sync.aligned.m16n8k16.row.col.f32.bf16.bf16.f32 "
        "{%0,%1,%2,%3},{%4,%5,%6,%7},{%8,%9},{%0,%1,%2,%3};"
        : "+f"(c[0]), "+f"(c[1]), "+f"(c[2]), "+f"(c[3])
        : "r"(a[0]), "r"(a[1]), "r"(a[2]), "r"(a[3]), "r"(b[0]), "r"(b[1]));
}

__global__ void vq_prep(const float* __restrict__ cb)
{
    __shared__ float sm[1024];
    int k = threadIdx.x;
    const float* r = cb + (size_t)k * EMBED;
    float s = 0.f, am = 0.f;
    #pragma unroll
    for (int d = 0; d < EMBED; ++d) {
        float v = r[d];
        s = fmaf(v, v, s);
        am = fmaxf(am, fabsf(v));
        g_cbb[k * CBS + d] = __float2bfloat16(v);
    }
    #pragma unroll
    for (int d = EMBED; d < CBS; ++d) g_cbb[k * CBS + d] = __float2bfloat16(0.f);
    g_esq[k] = s; g_hist[k] = 0; sm[k] = am;
    __syncthreads();
    for (int o = 512; o; o >>= 1) {
        if (k < o) sm[k] = fmaxf(sm[k], sm[k + o]);
        __syncthreads();
    }
    if (k == 0) g_emax = sm[0];
}

extern __shared__ unsigned char smraw[];

__global__ void __launch_bounds__(256, 1)
vq_main(const float* __restrict__ z, const float* __restrict__ cb,
        float* __restrict__ out)
{
    __half*        sc  = (__half*)(smraw + O_SC);
    __nv_bfloat16* cbf = (__nv_bfloat16*)(smraw + O_CB);
    __nv_bfloat16* zb  = (__nv_bfloat16*)(smraw + O_ZB);
    float*  seq = (float*)(smraw + O_EQ);
    float*  sdl = (float*)(smraw + O_DL);
    float*  szq = (float*)(smraw + O_ZQ);
    float*  s4  = (float*)(smraw + O_S4);
    int*    six = (int*)(smraw + O_IX);
    unsigned* qc = (unsigned*)(smraw + O_QC);
    unsigned* qu = (unsigned*)(smraw + O_QU);
    double* srd = (double*)(smraw + O_RD);

    const int tid = threadIdx.x;
    const int tb  = blockIdx.x * TOK_BLK;

    for (int i = tid; i < CHELEM / 8; i += 256) cp16(cbf + i * 8, g_cbb + i * 8);
    asm volatile("cp.async.commit_group;");
    for (int i = tid; i < CHELEM / 8; i += 256) cp16(cbf + CHELEM + i * 8, g_cbb + CHELEM + i * 8);
    asm volatile("cp.async.commit_group;");

    {   // z tile -> bf16 (padded) + abs-sums + e_sq copy
        int t = tid >> 2, q = tid & 3;
        const float4* zp = (const float4*)(z + (size_t)(tb + t) * EMBED + q * 16);
        float sa = 0.f;
        #pragma unroll
        for (int j = 0; j < 4; ++j) {
            float4 v = zp[j];
            sa += fabsf(v.x) + fabsf(v.y) + fabsf(v.z) + fabsf(v.w);
            __nv_bfloat162* d2 = (__nv_bfloat162*)(zb + t * CBS + q * 16 + j * 4);
            d2[0] = __floats2bfloat162_rn(v.x, v.y);
            d2[1] = __floats2bfloat162_rn(v.z, v.w);
        }
        s4[tid] = sa;
        if (tid < TOK_BLK * 2) {   // pad tail of zb rows (cols 64..71)
            int t2 = tid >> 1, h = tid & 1;
            *(__nv_bfloat162*)(zb + t2 * CBS + 64 + h * 4) = __floats2bfloat162_rn(0.f, 0.f);
            *(__nv_bfloat162*)(zb + t2 * CBS + 66 + h * 4) = __floats2bfloat162_rn(0.f, 0.f);
        }
        for (int i = tid; i < NCODES; i += 256) seq[i] = g_esq[i];
    }
    __syncthreads();
    if (tid < TOK_BLK)
        sdl[tid] = 0.025f * g_emax * (s4[tid*4] + s4[tid*4+1] + s4[tid*4+2] + s4[tid*4+3]) + 3e-4f;

    const int w = tid >> 5, l = tid & 31;
    const int gr = l >> 2, k0 = (l & 3) * 2;

    for (int c = 0; c < 4; ++c) {
        asm volatile("cp.async.wait_group 1;");
        __syncthreads();
        const __nv_bfloat16* se = cbf + (c & 1) * CHELEM;

        unsigned B[4][4][2]; float eq[4][2];
        #pragma unroll
        for (int j = 0; j < 4; ++j) {
            int cr = w * 32 + j * 8 + gr;
            #pragma unroll
            for (int ks = 0; ks < 4; ++ks) {
                B[j][ks][0] = *(const unsigned*)(se + cr * CBS + ks * 16 + k0);
                B[j][ks][1] = *(const unsigned*)(se + cr * CBS + ks * 16 + k0 + 8);
            }
            int col = c * 256 + w * 32 + j * 8 + k0;
            eq[j][0] = seq[col]; eq[j][1] = seq[col + 1];
        }
        #pragma unroll
        for (int rg = 0; rg < 2; ++rg) {
            unsigned A[2][4][4];
            #pragma unroll
            for (int rr = 0; rr < 2; ++rr) {
                int tr = rg * 32 + rr * 16 + gr;
                #pragma unroll
                for (int ks = 0; ks < 4; ++ks) {
                    A[rr][ks][0] = *(const unsigned*)(zb + tr * CBS + ks * 16 + k0);
                    A[rr][ks][1] = *(const unsigned*)(zb + (tr + 8) * CBS + ks * 16 + k0);
                    A[rr][ks][2] = *(const unsigned*)(zb + tr * CBS + ks * 16 + k0 + 8);
                    A[rr][ks][3] = *(const unsigned*)(zb + (tr + 8) * CBS + ks * 16 + k0 + 8);
                }
            }
            float C[2][4][4];
            #pragma unroll
            for (int rr = 0; rr < 2; ++rr)
                #pragma unroll
                for (int j = 0; j < 4; ++j)
                    #pragma unroll
                    for (int e = 0; e < 4; ++e) C[rr][j][e] = 0.f;
            #pragma unroll
            for (int ks = 0; ks < 4; ++ks)
                #pragma unroll
                for (int rr = 0; rr < 2; ++rr)
                    #pragma unroll
                    for (int j = 0; j < 4; ++j)
                        mma16816(C[rr][j], A[rr][ks], B[j][ks]);
            #pragma unroll
            for (int rr = 0; rr < 2; ++rr) {
                int tr = rg * 32 + rr * 16 + gr;
                #pragma unroll
                for (int j = 0; j < 4; ++j) {
                    int col = c * 256 + w * 32 + j * 8 + k0;
                    *(__half2*)(sc + tr * SCS + col) =
                        __floats2half2_rn(fmaf(-2.f, C[rr][j][0], eq[j][0]),
                                          fmaf(-2.f, C[rr][j][1], eq[j][1]));
                    *(__half2*)(sc + (tr + 8) * SCS + col) =
                        __floats2half2_rn(fmaf(-2.f, C[rr][j][2], eq[j][0]),
                                          fmaf(-2.f, C[rr][j][3], eq[j][1]));
                }
            }
        }
        __syncthreads();
        if (c + 2 < 4) {
            const __nv_bfloat16* s = g_cbb + (c + 2) * CHELEM;
            __nv_bfloat16*       d = cbf + (c & 1) * CHELEM;
            for (int i = tid; i < CHELEM / 8; i += 256) cp16(d + i * 8, s + i * 8);
        }
        asm volatile("cp.async.commit_group;");
    }

    // ---- scan: warp w owns tokens [8w, 8w+8) ----
    if (l < 8) {
        int t = w * 8 + l;
        const float* zp = z + (size_t)(tb + t) * EMBED;
        float s = 0.f;
        #pragma unroll
        for (int d = 0; d < EMBED; ++d) s = fmaf(zp[d], zp[d], s);
        szq[t] = s;
    }
    if (l == 0) qc[w] = 0;
    __syncwarp();

    float thr[8];
    #pragma unroll
    for (int r = 0; r < 8; ++r) {
        const __half* sr = sc + (w * 8 + r) * SCS + l * 32;
        float m = 3.4e38f;
        #pragma unroll
        for (int i = 0; i < 4; ++i) {
            uint4 v = *(const uint4*)(sr + i * 8);
            const __half2* h = (const __half2*)&v;
            #pragma unroll
            for (int p = 0; p < 4; ++p) {
                float2 f = __half22float2(h[p]);
                m = fminf(m, fminf(f.x, f.y));
            }
        }
        #pragma unroll
        for (int o = 16; o; o >>= 1) m = fminf(m, __shfl_xor_sync(~0u, m, o));
        thr[r] = m + sdl[w * 8 + r];
    }

    bool ovf = false;
    #pragma unroll
    for (int r = 0; r < 8; ++r) {
        const __half* sr = sc + (w * 8 + r) * SCS + l * 32;
        #pragma unroll
        for (int i = 0; i < 4; ++i) {
            uint4 v = *(const uint4*)(sr + i * 8);
            const __half* h = (const __half*)&v;
            #pragma unroll
            for (int p = 0; p < 8; ++p)
                if (__half2float(h[p]) <= thr[r]) {
                    unsigned pos = atomicAdd(&qc[w], 1u);
                    if (pos < QCAP)
                        qu[w * QCAP + pos] = ((unsigned)(w * 8 + r) << 16) | (unsigned)(l * 32 + i * 8 + p);
                    else ovf = true;
                }
        }
    }
    __syncwarp();
    ovf = __any_sync(~0u, ovf);

    float bs[8]; int bk[8];
    #pragma unroll
    for (int r = 0; r < 8; ++r) { bs[r] = 3.4e38f; bk[r] = 0x7fffffff; }

    if (!ovf) {
        unsigned n = qc[w];
        for (unsigned b = 0; b < n; b += 32) {
            unsigned i = b + l;
            if (i < n) {
                unsigned e = qu[w * QCAP + i];
                int t = (int)(e >> 16), k = (int)(e & 0xffffu);
                const float* zp = z + (size_t)(tb + t) * EMBED;
                const float* ep = cb + (size_t)k * EMBED;
                float dot = 0.f;
                #pragma unroll
                for (int d = 0; d < EMBED; ++d) dot = fmaf(zp[d], ep[d], dot);
                float s = fmaf(-2.f, dot, szq[t]) + g_esq[k];
                int r = t - w * 8;
                if (s < bs[r] || (s == bs[r] && k < bk[r])) { bs[r] = s; bk[r] = k; }
            }
        }
    } else {
        for (int r = 0; r < 8; ++r) {
            int t = w * 8 + r;
            const __half* sr = sc + t * SCS + l * 32;
            for (int i = 0; i < 32; ++i)
                if (__half2float(sr[i]) <= thr[r]) {
                    int k = l * 32 + i;
                    const float* zp = z + (size_t)(tb + t) * EMBED;
                    const float* ep = cb + (size_t)k * EMBED;
                    float dot = 0.f;
                    for (int d = 0; d < EMBED; ++d) dot = fmaf(zp[d], ep[d], dot);
                    float s = fmaf(-2.f, dot, szq[t]) + g_esq[k];
                    if (s < bs[r] || (s == bs[r] && k < bk[r])) { bs[r] = s; bk[r] = k; }
                }
        }
    }

    #pragma unroll
    for (int r = 0; r < 8; ++r) {
        float s = bs[r]; int k = bk[r];
        #pragma unroll
        for (int o = 16; o; o >>= 1) {
            float s2 = __shfl_xor_sync(~0u, s, o);
            int   k2 = __shfl_xor_sync(~0u, k, o);
            if (s2 < s || (s2 == s && k2 < k)) { s = s2; k = k2; }
        }
        if (l == 0) {
            six[w * 8 + r] = k;
            out[(size_t)N_TOKENS * EMBED + tb + w * 8 + r] = (float)k;
        }
    }
    __syncthreads();

    // ---- fused STE + MSE partial + histogram ----
    {
        int t = tid >> 2, q = tid & 3;
        int idx = six[t];
        const float* cp = cb + (size_t)idx * EMBED + q * 16;
        const float* zp = z + (size_t)(tb + t) * EMBED + q * 16;
        float*       op = out + (size_t)(tb + t) * EMBED + q * 16;
        double acc = 0.0;
        #pragma unroll
        for (int j = 0; j < 4; ++j) {
            float4 e = *(const float4*)(cp + j * 4);
            float4 v = *(const float4*)(zp + j * 4);
            float dx = e.x - v.x, dy = e.y - v.y, dz = e.z - v.z, dw = e.w - v.w;
            *(float4*)(op + j * 4) = make_float4(v.x + dx, v.y + dy, v.z + dz, v.w + dw);
            acc += (double)(dx*dx) + (double)(dy*dy) + (double)(dz*dz) + (double)(dw*dw);
        }
        srd[tid] = acc;
        __syncthreads();
        #pragma unroll
        for (int o = 128; o; o >>= 1) {
            if (tid < o) srd[tid] += srd[tid + o];
            __syncthreads();
        }
        if (tid == 0) g_partial[blockIdx.x] = srd[0];
        if (q == 0) atomicAdd(&g_hist[idx], 1);
    }
}

__global__ void __launch_bounds__(1024)
vq_final(float* __restrict__ out)
{
    __shared__ double sr[1024];
    __shared__ double sl;
    const int tid = threadIdx.x;
    sr[tid] = g_partial[tid] + g_partial[tid + 1024];
    __syncthreads();
    #pragma unroll
    for (int o = 512; o; o >>= 1) {
        if (tid < o) sr[tid] += sr[tid + o];
        __syncthreads();
    }
    if (tid == 0) sl = sr[0];
    __syncthreads();
    {
        float p = (float)g_hist[tid] / 131072.0f + 1e-10f;
        sr[tid] = (double)(p * logf(p));
    }
    __syncthreads();
    #pragma unroll
    for (int o = 512; o; o >>= 1) {
        if (tid < o) sr[tid] += sr[tid + o];
        __syncthreads();
    }
    if (tid == 0) {
        const size_t b = (size_t)N_TOKENS * EMBED + N_TOKENS;
        float cl = (float)(sl / (double)((size_t)N_TOKENS * EMBED));
        float en = (float)(-sr[0]);
        out[b + 0] = cl;
        out[b + 1] = 0.25f * cl;
        out[b + 2] = -0.1f * (en / 6.9314718055994531f);
        out[b + 3] = expf(en);
    }
}

extern "C" void kernel_launch(void* const* d_in, const int* in_sizes, int n_in,
                              void* d_out, int out_size)
{
    const float* z  = (const float*)d_in[0];
    const float* cb = (const float*)d_in[1];
    float* out = (float*)d_out;

    static bool done = false;
    if (!done) {
        cudaFuncSetAttribute(vq_main, cudaFuncAttributeMaxDynamicSharedMemorySize, SMEMSZ);
        done = true;
    }
    vq_prep<<<1, 1024>>>(cb);
    vq_main<<<NBLK, 256, SMEMSZ>>>(z, cb, out);
    vq_final<<<1, 1024>>>(out);
}

// round 7
// speedup vs baseline: 1.9596x; 1.4607x over previous
#include <cuda_runtime.h>
#include <cuda_fp16.h>
#include <cuda_bf16.h>
#include <cstdint>

#define NT    131072
#define NCODE 1024
#define TOKB  64
#define NBLK  (NT / TOKB)          // 2048
#define CBS   72                    // bf16 A/B smem row stride (halves)
#define SCS   1032                  // fp16 score row stride (halves)
#define QCAP  512

__device__ float  g_esq[NCODE];
__device__ float  g_emaxb[128];
__device__ int    g_hist[NCODE];
__device__ double g_partial[NBLK];
__device__ __nv_bfloat16 g_cbb[NCODE * 64];

// ---- smem byte offsets ----
#define O_A   0          // bf16 [64][72]            9216
#define O_B   9216       // bf16 [2][256][72]        73728
#define O_SC  82944      // half [64][1032]          132096
#define O_EQ  215040     // float[1024]
#define O_ZQ  219136     // float[64]
#define O_SD  219392     // float[64]
#define O_MN  219648     // uint [64]
#define O_EM  219904     // float[128]
#define O_CD  220416     // u64  [64]
#define O_QU  220928     // u32  [512]
#define O_QC  222976     // u32 x2
#define O_RD  222984     // double[256]
#define SMEMSZ 225032

static __device__ __forceinline__ void mma16816(float* c, const unsigned* a, const unsigned* b) {
    asm volatile(
        "mma.sync.aligned.m16n8k16.row.col.f32.bf16.bf16.f32 "
        "{%0,%1,%2,%3},{%4,%5,%6,%7},{%8,%9},{%0,%1,%2,%3};"
        : "+f"(c[0]), "+f"(c[1]), "+f"(c[2]), "+f"(c[3])
        : "r"(a[0]), "r"(a[1]), "r"(a[2]), "r"(a[3]), "r"(b[0]), "r"(b[1]));
}
static __device__ __forceinline__ unsigned long long packkey(float s, int k) {
    unsigned u = __float_as_uint(s);
    u = ((int)u < 0) ? ~u : (u | 0x80000000u);
    return ((unsigned long long)u << 32) | (unsigned)k;
}
static __device__ __forceinline__ float exact_score(const float4* zr, const float4* cr,
                                                    float zsq, float esq) {
    float dot = 0.f;
    #pragma unroll
    for (int m = 0; m < 16; ++m) {
        float4 a = zr[m], b = cr[m];
        dot = fmaf(a.x, b.x, dot); dot = fmaf(a.y, b.y, dot);
        dot = fmaf(a.z, b.z, dot); dot = fmaf(a.w, b.w, dot);
    }
    return fmaf(-2.f, dot, zsq) + esq;
}

// ---------------- prep: warp-per-code, 128 blocks ----------------
__global__ void __launch_bounds__(256) vq_prep(const float* __restrict__ cb)
{
    __shared__ float wm[8];
    int w = threadIdx.x >> 5, l = threadIdx.x & 31;
    int k = blockIdx.x * 8 + w;
    float2 v = ((const float2*)(cb + (size_t)k * 64))[l];
    float sq = fmaf(v.y, v.y, v.x * v.x);
    float am = fmaxf(fabsf(v.x), fabsf(v.y));
    #pragma unroll
    for (int o = 16; o; o >>= 1) {
        sq += __shfl_xor_sync(~0u, sq, o);
        am = fmaxf(am, __shfl_xor_sync(~0u, am, o));
    }
    ((__nv_bfloat162*)(g_cbb + (size_t)k * 64))[l] = __floats2bfloat162_rn(v.x, v.y);
    if (l == 0) { g_esq[k] = sq; wm[w] = am; }
    __syncthreads();
    if (threadIdx.x == 0) {
        float m = wm[0];
        #pragma unroll
        for (int i = 1; i < 8; ++i) m = fmaxf(m, wm[i]);
        g_emaxb[blockIdx.x] = m;
    }
    if (threadIdx.x < 8) g_hist[blockIdx.x * 8 + threadIdx.x] = 0;
}

// ---------------- main ----------------
extern __shared__ unsigned char smraw[];

__global__ void __launch_bounds__(256, 1)
vq_main(const float* __restrict__ z, const float* __restrict__ cb, float* __restrict__ out)
{
    __nv_bfloat16* sa = (__nv_bfloat16*)(smraw + O_A);
    __nv_bfloat16* sB = (__nv_bfloat16*)(smraw + O_B);
    __half* sc  = (__half*)(smraw + O_SC);
    float* seq  = (float*)(smraw + O_EQ);
    float* szq  = (float*)(smraw + O_ZQ);
    float* sdl  = (float*)(smraw + O_SD);
    unsigned* smn = (unsigned*)(smraw + O_MN);
    float* sem  = (float*)(smraw + O_EM);
    unsigned long long* cand = (unsigned long long*)(smraw + O_CD);
    unsigned* qu = (unsigned*)(smraw + O_QU);
    unsigned* qc = (unsigned*)(smraw + O_QC);
    double* srd = (double*)(smraw + O_RD);

    const int tid = threadIdx.x, w = tid >> 5, l = tid & 31;
    const int tb = blockIdx.x * TOKB;
    const int gr = l >> 2, k0 = (l & 3) * 2;
    const unsigned sBsh = (unsigned)__cvta_generic_to_shared(sB);

    // prefetch B chunks 0,1
    #pragma unroll 1
    for (int cc = 0; cc < 2; ++cc) {
        const __nv_bfloat16* src = g_cbb + cc * 256 * 64;
        unsigned dst = sBsh + cc * 36864;
        for (int i = tid; i < 2048; i += 256) {
            int code = i >> 3, seg = i & 7;
            asm volatile("cp.async.cg.shared.global [%0], [%1], 16;"
                         :: "r"(dst + code * 144 + seg * 16), "l"(src + code * 64 + seg * 8));
        }
        asm volatile("cp.async.commit_group;");
    }
    {   // stage A (bf16, stride 72)
        int t = tid >> 2, q = tid & 3;
        const float4* zp = (const float4*)(z + (size_t)(tb + t) * 64 + q * 16);
        #pragma unroll
        for (int j = 0; j < 4; ++j) {
            float4 v = zp[j];
            __nv_bfloat162* d = (__nv_bfloat162*)(sa + t * CBS + q * 16 + j * 4);
            d[0] = __floats2bfloat162_rn(v.x, v.y);
            d[1] = __floats2bfloat162_rn(v.z, v.w);
        }
    }
    if (tid < 128) sem[tid] = g_emaxb[tid];
    if (tid < 64) { smn[tid] = 0xFFFFFFFFu; cand[tid] = ~0ULL; }
    if (tid == 0) { qc[0] = 0; qc[1] = 0; }
    if (l < 8) {   // exact z_sq + abs-sum
        int t = w * 8 + l;
        const float* zp = z + (size_t)(tb + t) * 64;
        float s = 0.f, a = 0.f;
        #pragma unroll
        for (int d = 0; d < 64; ++d) { float v = zp[d]; s = fmaf(v, v, s); a += fabsf(v); }
        szq[t] = s; sdl[t] = a;
    }
    for (int i = tid; i < NCODE; i += 256) seq[i] = g_esq[i];
    __syncthreads();
    if (tid < 64) {
        float em = sem[0];
        #pragma unroll
        for (int i = 1; i < 128; ++i) em = fmaxf(em, sem[i]);
        sdl[tid] = 0.025f * em * sdl[tid] + 3e-4f;
    }

    // hoist A fragments (reused across all 4 chunks)
    unsigned Ar[4][4][4];
    #pragma unroll
    for (int m = 0; m < 4; ++m)
        #pragma unroll
        for (int ks = 0; ks < 4; ++ks) {
            int r0 = (m * 16 + gr) * CBS + ks * 16 + k0;
            Ar[m][ks][0] = *(const unsigned*)(sa + r0);
            Ar[m][ks][1] = *(const unsigned*)(sa + r0 + 8 * CBS);
            Ar[m][ks][2] = *(const unsigned*)(sa + r0 + 8);
            Ar[m][ks][3] = *(const unsigned*)(sa + r0 + 8 * CBS + 8);
        }
    float minv[8];
    #pragma unroll
    for (int i = 0; i < 8; ++i) minv[i] = 3.4e38f;

    #pragma unroll 1
    for (int c = 0; c < 4; ++c) {
        asm volatile("cp.async.wait_group 1;");
        __syncthreads();
        const __nv_bfloat16* bb = sB + (c & 1) * 18432;
        #pragma unroll
        for (int j = 0; j < 4; ++j) {
            unsigned Br[4][2];
            int brow = (w * 32 + j * 8 + gr) * CBS + k0;
            #pragma unroll
            for (int ks = 0; ks < 4; ++ks) {
                Br[ks][0] = *(const unsigned*)(bb + brow + ks * 16);
                Br[ks][1] = *(const unsigned*)(bb + brow + ks * 16 + 8);
            }
            int cbase = c * 256 + w * 32 + j * 8 + k0;
            float eqA = seq[cbase], eqB = seq[cbase + 1];
            float C[4][4];
            #pragma unroll
            for (int m = 0; m < 4; ++m) { C[m][0] = 0; C[m][1] = 0; C[m][2] = 0; C[m][3] = 0; }
            #pragma unroll
            for (int ks = 0; ks < 4; ++ks)
                #pragma unroll
                for (int m = 0; m < 4; ++m) mma16816(C[m], Ar[m][ks], Br[ks]);
            #pragma unroll
            for (int m = 0; m < 4; ++m) {
                float s0 = fmaf(-2.f, C[m][0], eqA), s1 = fmaf(-2.f, C[m][1], eqB);
                float s2 = fmaf(-2.f, C[m][2], eqA), s3 = fmaf(-2.f, C[m][3], eqB);
                int t0 = m * 16 + gr;
                *(__half2*)(sc + t0 * SCS + cbase)       = __floats2half2_rn(s0, s1);
                *(__half2*)(sc + (t0 + 8) * SCS + cbase) = __floats2half2_rn(s2, s3);
                minv[2 * m]     = fminf(minv[2 * m], fminf(s0, s1));
                minv[2 * m + 1] = fminf(minv[2 * m + 1], fminf(s2, s3));
            }
        }
        __syncthreads();
        if (c + 2 < 4) {
            const __nv_bfloat16* src = g_cbb + (c + 2) * 256 * 64;
            unsigned dst = sBsh + (c & 1) * 36864;
            for (int i = tid; i < 2048; i += 256) {
                int code = i >> 3, seg = i & 7;
                asm volatile("cp.async.cg.shared.global [%0], [%1], 16;"
                             :: "r"(dst + code * 144 + seg * 16), "l"(src + code * 64 + seg * 8));
            }
        }
        asm volatile("cp.async.commit_group;");
    }

    // per-token min: quad shuffle + smem atomicMin (monotone uint map)
    #pragma unroll
    for (int i = 0; i < 8; ++i) {
        float m = minv[i];
        m = fminf(m, __shfl_xor_sync(~0u, m, 1));
        m = fminf(m, __shfl_xor_sync(~0u, m, 2));
        if ((l & 3) == 0) {
            int t = (i >> 1) * 16 + gr + (i & 1) * 8;
            unsigned u = __float_as_uint(m);
            u = ((int)u < 0) ? ~u : (u | 0x80000000u);
            atomicMin(&smn[t], u);
        }
    }
    __syncthreads();

    // candidate pass: warp w scans tokens [8w, 8w+8)
    #pragma unroll 1
    for (int r = 0; r < 8; ++r) {
        int t = w * 8 + r;
        unsigned u = smn[t];
        float mn = __uint_as_float((u & 0x80000000u) ? (u & 0x7FFFFFFFu) : ~u);
        float thr = mn + sdl[t];
        const __half* srow = sc + t * SCS + l * 32;
        #pragma unroll
        for (int i = 0; i < 4; ++i) {
            uint4 v = *(const uint4*)(srow + i * 8);
            const __half* h = (const __half*)&v;
            #pragma unroll
            for (int p = 0; p < 8; ++p)
                if (__half2float(h[p]) <= thr) {
                    unsigned pos = atomicAdd(qc, 1u);
                    if (pos < QCAP) qu[pos] = ((unsigned)t << 16) | (unsigned)(l * 32 + i * 8 + p);
                    else qc[1] = 1;
                }
        }
    }
    __syncthreads();

    // exact rescore
    if (!qc[1]) {
        unsigned n = qc[0];
        for (unsigned i = tid; i < n; i += 256) {
            unsigned e = qu[i];
            int t = (int)(e >> 16), k = (int)(e & 0xffffu);
            float s = exact_score((const float4*)(z + (size_t)(tb + t) * 64),
                                  (const float4*)(cb + (size_t)k * 64), szq[t], seq[k]);
            atomicMin(&cand[t], packkey(s, k));
        }
    } else {   // overflow: full exact scan (practically never)
        int t = tid >> 2, kb = (tid & 3) * 256;
        unsigned long long best = ~0ULL;
        for (int k = kb; k < kb + 256; ++k) {
            float s = exact_score((const float4*)(z + (size_t)(tb + t) * 64),
                                  (const float4*)(cb + (size_t)k * 64), szq[t], seq[k]);
            unsigned long long p = packkey(s, k);
            if (p < best) best = p;
        }
        atomicMin(&cand[t], best);
    }
    __syncthreads();

    // outputs: index, STE, MSE partial, hist
    {
        int t = tid >> 2, q = tid & 3;
        int idx = (int)(unsigned)cand[t];
        if (q == 0) {
            out[(size_t)NT * 64 + tb + t] = (float)idx;
            atomicAdd(&g_hist[idx], 1);
        }
        const float4* cp = (const float4*)(cb + (size_t)idx * 64 + q * 16);
        const float4* zp = (const float4*)(z + (size_t)(tb + t) * 64 + q * 16);
        float4*       op = (float4*)(out + (size_t)(tb + t) * 64 + q * 16);
        double acc = 0.0;
        #pragma unroll
        for (int j2 = 0; j2 < 4; ++j2) {
            float4 e = cp[j2], v = zp[j2];
            float dx = e.x - v.x, dy = e.y - v.y, dz = e.z - v.z, dw = e.w - v.w;
            op[j2] = make_float4(v.x + dx, v.y + dy, v.z + dz, v.w + dw);
            acc += (double)(dx * dx) + (double)(dy * dy) + (double)(dz * dz) + (double)(dw * dw);
        }
        srd[tid] = acc;
    }
    __syncthreads();
    #pragma unroll
    for (int o = 128; o; o >>= 1) {
        if (tid < o) srd[tid] += srd[tid + o];
        __syncthreads();
    }
    if (tid == 0) g_partial[blockIdx.x] = srd[0];
}

// ---------------- final ----------------
__global__ void __launch_bounds__(1024) vq_final(float* __restrict__ out)
{
    __shared__ double sr[1024];
    __shared__ double sl;
    const int tid = threadIdx.x;
    sr[tid] = g_partial[tid] + g_partial[tid + 1024];
    __syncthreads();
    #pragma unroll
    for (int o = 512; o; o >>= 1) {
        if (tid < o) sr[tid] += sr[tid + o];
        __syncthreads();
    }
    if (tid == 0) sl = sr[0];
    __syncthreads();
    {
        float p = (float)g_hist[tid] / 131072.0f + 1e-10f;
        sr[tid] = (double)(p * logf(p));
    }
    __syncthreads();
    #pragma unroll
    for (int o = 512; o; o >>= 1) {
        if (tid < o) sr[tid] += sr[tid + o];
        __syncthreads();
    }
    if (tid == 0) {
        const size_t b = (size_t)NT * 64 + NT;
        float cl = (float)(sl / (double)((size_t)NT * 64));
        float en = (float)(-sr[0]);
        out[b + 0] = cl;
        out[b + 1] = 0.25f * cl;
        out[b + 2] = -0.1f * (en / 6.9314718055994531f);
        out[b + 3] = expf(en);
    }
}

extern "C" void kernel_launch(void* const* d_in, const int* in_sizes, int n_in,
                              void* d_out, int out_size)
{
    const float* z  = (const float*)d_in[0];
    const float* cb = (const float*)d_in[1];
    float* out = (float*)d_out;
    static bool done = false;
    if (!done) {
        cudaFuncSetAttribute(vq_main, cudaFuncAttributeMaxDynamicSharedMemorySize, SMEMSZ);
        done = true;
    }
    vq_prep<<<128, 256>>>(cb);
    vq_main<<<NBLK, 256, SMEMSZ>>>(z, cb, out);
    vq_final<<<1, 1024>>>(out);
}

// round 8
// speedup vs baseline: 2.2762x; 1.1616x over previous
#include <cuda_runtime.h>
#include <cstdint>

#define NT 131072
#define NCODE 1024
#define TOKB 64
#define NBLK (NT / TOKB)
#define QCAP 768

__device__ float  g_esq[NCODE];
__device__ float  g_emaxb[128];
__device__ int    g_s8b[64];
__device__ int    g_hist[NCODE];
__device__ double g_partial[NBLK];
__device__ unsigned g_cbq[NCODE * 16];   // s8-packed codebook rows (64 B/code)

// ---- smem byte offsets ----
#define O_A   0        // s8 [64][80]              5120
#define O_B   5120     // s8 [2][256][80]          40960
#define O_EQ  46080    // float[1024]              4096
#define O_ZQ  50176    // float[64]
#define O_DL  50432    // float[64]
#define O_SF  50688    // float[64]  (-2*se*sz)
#define O_ISZ 50944    // float[64]  (127/zamax)
#define O_MN  51200    // uint [64]
#define O_CD  51456    // u64  [64]                512
#define O_QU  51968    // u32  [768]               3072
#define O_QC  55040    // u32 x2
#define O_P   55048    // float[3][256]            3072
#define O_RD  58120    // double[256]              2048
#define SMEMSZ 60168

static __device__ __forceinline__ void imma(int* c, const unsigned* a, const unsigned* b) {
    asm volatile("mma.sync.aligned.m16n8k32.row.col.s32.s8.s8.s32 "
        "{%0,%1,%2,%3},{%4,%5,%6,%7},{%8,%9},{%0,%1,%2,%3};"
        : "+r"(c[0]), "+r"(c[1]), "+r"(c[2]), "+r"(c[3])
        : "r"(a[0]), "r"(a[1]), "r"(a[2]), "r"(a[3]), "r"(b[0]), "r"(b[1]));
}
static __device__ __forceinline__ unsigned long long packkey(float s, int k) {
    unsigned u = __float_as_uint(s);
    u = ((int)u < 0) ? ~u : (u | 0x80000000u);
    return ((unsigned long long)u << 32) | (unsigned)k;
}
static __device__ __forceinline__ float unmap(unsigned u) {
    return __uint_as_float((u & 0x80000000u) ? (u & 0x7FFFFFFFu) : ~u);
}
static __device__ __forceinline__ float exact_score(const float4* zr, const float4* cr,
                                                    float zsq, float esq) {
    float dot = 0.f;
    #pragma unroll
    for (int m = 0; m < 16; ++m) {
        float4 a = zr[m], b = cr[m];
        dot = fmaf(a.x, b.x, dot); dot = fmaf(a.y, b.y, dot);
        dot = fmaf(a.z, b.z, dot); dot = fmaf(a.w, b.w, dot);
    }
    return fmaf(-2.f, dot, zsq) + esq;
}

// ---------------- prep1: esq, emax per block, zero hist ----------------
__global__ void __launch_bounds__(256) vq_prep(const float* __restrict__ cb)
{
    __shared__ float wm[8];
    int w = threadIdx.x >> 5, l = threadIdx.x & 31;
    int k = blockIdx.x * 8 + w;
    float2 v = ((const float2*)(cb + (size_t)k * 64))[l];
    float sq = fmaf(v.y, v.y, v.x * v.x);
    float am = fmaxf(fabsf(v.x), fabsf(v.y));
    #pragma unroll
    for (int o = 16; o; o >>= 1) {
        sq += __shfl_xor_sync(~0u, sq, o);
        am = fmaxf(am, __shfl_xor_sync(~0u, am, o));
    }
    if (l == 0) { g_esq[k] = sq; wm[w] = am; }
    __syncthreads();
    if (threadIdx.x == 0) {
        float m = wm[0];
        #pragma unroll
        for (int i = 1; i < 8; ++i) m = fmaxf(m, wm[i]);
        g_emaxb[blockIdx.x] = m;
    }
    if (threadIdx.x < 8) g_hist[blockIdx.x * 8 + threadIdx.x] = 0;
}

// ---------------- prep2: quantize codebook to s8, per-block S8 max ----------------
__global__ void __launch_bounds__(256) vq_quant(const float* __restrict__ cb)
{
    __shared__ float sm[128];
    __shared__ int scode[16];
    int tid = threadIdx.x;
    if (tid < 128) sm[tid] = g_emaxb[tid];
    __syncthreads();
    if (tid == 0) {
        float m = sm[0];
        for (int i = 1; i < 128; ++i) m = fmaxf(m, sm[i]);
        sm[0] = m;
    }
    __syncthreads();
    float inv_se = 127.f / sm[0];
    int code = blockIdx.x * 16 + (tid >> 4), q = tid & 15;
    float4 v = *(const float4*)(cb + (size_t)code * 64 + q * 4);
    int a = __float2int_rn(v.x * inv_se), b = __float2int_rn(v.y * inv_se);
    int c = __float2int_rn(v.z * inv_se), d = __float2int_rn(v.w * inv_se);
    g_cbq[code * 16 + q] = (a & 255) | ((b & 255) << 8) | ((c & 255) << 16) | ((d & 255) << 24);
    int s = abs(a) + abs(b) + abs(c) + abs(d);
    #pragma unroll
    for (int o = 8; o; o >>= 1) s += __shfl_down_sync(~0u, s, o, 16);
    if (q == 0) scode[tid >> 4] = s;
    __syncthreads();
    if (tid == 0) {
        int m = scode[0];
        #pragma unroll
        for (int i = 1; i < 16; ++i) m = max(m, scode[i]);
        g_s8b[blockIdx.x] = m;
    }
}

// ---------------- main ----------------
extern __shared__ unsigned char smraw[];

__global__ void __launch_bounds__(256, 2)
vq_main(const float* __restrict__ z, const float* __restrict__ cb, float* __restrict__ out)
{
    signed char* sA = (signed char*)(smraw + O_A);
    signed char* sB = (signed char*)(smraw + O_B);
    float* seq  = (float*)(smraw + O_EQ);
    float* szq  = (float*)(smraw + O_ZQ);
    float* sdl  = (float*)(smraw + O_DL);
    float* ssf  = (float*)(smraw + O_SF);
    float* sisz = (float*)(smraw + O_ISZ);
    unsigned* smn = (unsigned*)(smraw + O_MN);
    unsigned long long* cand = (unsigned long long*)(smraw + O_CD);
    unsigned* qu = (unsigned*)(smraw + O_QU);
    unsigned* qc = (unsigned*)(smraw + O_QC);
    float* psq = (float*)(smraw + O_P);
    float* pab = psq + 256;
    float* pmx = psq + 512;
    double* srd = (double*)(smraw + O_RD);

    const int tid = threadIdx.x, w = tid >> 5, l = tid & 31;
    const int tb = blockIdx.x * TOKB;
    const int gr = l >> 2, tig = l & 3;
    const unsigned sBsh = (unsigned)__cvta_generic_to_shared(sB);
    const char* cbq = (const char*)g_cbq;

    // prefetch B chunks 0,1 (s8, 64 B/code -> stride 80)
    #pragma unroll
    for (int cc = 0; cc < 2; ++cc) {
        for (int i = tid; i < 1024; i += 256) {
            int code = i >> 2, seg = i & 3;
            asm volatile("cp.async.cg.shared.global [%0], [%1], 16;"
                :: "r"(sBsh + cc * 20480 + code * 80 + seg * 16),
                   "l"(cbq + (size_t)(cc * 256 + code) * 64 + seg * 16));
        }
        asm volatile("cp.async.commit_group;");
    }

    // z tile: load fp32 (keep in regs), partial sq/abs/max; stash emaxb/s8b in qu
    const int t = tid >> 2, q = tid & 3;
    float4 zr[4];
    {
        const float4* zp = (const float4*)(z + (size_t)(tb + t) * 64 + q * 16);
        float ps = 0.f, pa = 0.f, pm = 0.f;
        #pragma unroll
        for (int j = 0; j < 4; ++j) {
            float4 v = zp[j]; zr[j] = v;
            ps = fmaf(v.x, v.x, ps); ps = fmaf(v.y, v.y, ps);
            ps = fmaf(v.z, v.z, ps); ps = fmaf(v.w, v.w, ps);
            pa += fabsf(v.x) + fabsf(v.y) + fabsf(v.z) + fabsf(v.w);
            pm = fmaxf(pm, fmaxf(fmaxf(fabsf(v.x), fabsf(v.y)), fmaxf(fabsf(v.z), fabsf(v.w))));
        }
        psq[tid] = ps; pab[tid] = pa; pmx[tid] = pm;
    }
    if (tid < 128) ((float*)qu)[tid] = g_emaxb[tid];
    if (tid < 64) { ((int*)qu)[128 + tid] = g_s8b[tid]; smn[tid] = 0xFFFFFFFFu; cand[tid] = ~0ULL; }
    if (tid == 0) { qc[0] = 0; qc[1] = 0; }
    for (int i = tid; i < NCODE; i += 256) seq[i] = g_esq[i];
    __syncthreads();

    if (tid < 64) {
        float em = ((float*)qu)[0];
        #pragma unroll
        for (int i = 1; i < 128; ++i) em = fmaxf(em, ((float*)qu)[i]);
        int S8 = ((int*)qu)[128];
        #pragma unroll
        for (int i = 1; i < 64; ++i) S8 = max(S8, ((int*)qu)[128 + i]);
        float zq_ = psq[tid * 4] + psq[tid * 4 + 1] + psq[tid * 4 + 2] + psq[tid * 4 + 3];
        float ab  = pab[tid * 4] + pab[tid * 4 + 1] + pab[tid * 4 + 2] + pab[tid * 4 + 3];
        float mx  = fmaxf(fmaxf(pmx[tid * 4], pmx[tid * 4 + 1]), fmaxf(pmx[tid * 4 + 2], pmx[tid * 4 + 3]));
        float se = em * (1.f / 127.f);
        float zm = fmaxf(mx, 1e-30f);
        float sz = zm * (1.f / 127.f);
        szq[tid] = zq_;
        ssf[tid] = -2.f * se * sz;
        sdl[tid] = se * (ab + sz * (float)S8) + 1e-4f;
        sisz[tid] = 127.f / zm;
    }
    __syncthreads();

    // quantize A into smem s8 (stride 80)
    {
        float isz = sisz[t];
        #pragma unroll
        for (int j = 0; j < 4; ++j) {
            float4 v = zr[j];
            int a = __float2int_rn(v.x * isz), b = __float2int_rn(v.y * isz);
            int c = __float2int_rn(v.z * isz), d = __float2int_rn(v.w * isz);
            *(unsigned*)(sA + t * 80 + q * 16 + j * 4) =
                (a & 255) | ((b & 255) << 8) | ((c & 255) << 16) | ((d & 255) << 24);
        }
    }
    asm volatile("cp.async.wait_group 1;");
    __syncthreads();

    // hoist A fragments: 4 m-tiles x 2 k-halves x 4 regs
    unsigned Ar[4][2][4];
    #pragma unroll
    for (int m = 0; m < 4; ++m)
        #pragma unroll
        for (int kh = 0; kh < 2; ++kh) {
            int base = (m * 16 + gr) * 80 + tig * 4 + kh * 32;
            Ar[m][kh][0] = *(const unsigned*)(sA + base);
            Ar[m][kh][1] = *(const unsigned*)(sA + base + 640);
            Ar[m][kh][2] = *(const unsigned*)(sA + base + 16);
            Ar[m][kh][3] = *(const unsigned*)(sA + base + 656);
        }
    float sf2[4][2];
    #pragma unroll
    for (int m = 0; m < 4; ++m) {
        sf2[m][0] = ssf[m * 16 + gr];
        sf2[m][1] = ssf[m * 16 + gr + 8];
    }
    float minv[8];
    #pragma unroll
    for (int i = 0; i < 8; ++i) minv[i] = 3.4e38f;
    float thrv[8];
    #pragma unroll
    for (int i = 0; i < 8; ++i) thrv[i] = 0.f;

    auto pass = [&](const signed char* bb, int cbase, bool enq) {
        #pragma unroll
        for (int j = 0; j < 4; ++j) {
            int crow = (w * 32 + j * 8 + gr) * 80 + tig * 4;
            unsigned B0[2], B1[2];
            B0[0] = *(const unsigned*)(bb + crow);
            B0[1] = *(const unsigned*)(bb + crow + 16);
            B1[0] = *(const unsigned*)(bb + crow + 32);
            B1[1] = *(const unsigned*)(bb + crow + 48);
            int col = cbase + w * 32 + j * 8 + tig * 2;
            float eqA = seq[col], eqB = seq[col + 1];
            int C[4][4];
            #pragma unroll
            for (int m = 0; m < 4; ++m) { C[m][0] = 0; C[m][1] = 0; C[m][2] = 0; C[m][3] = 0; }
            #pragma unroll
            for (int m = 0; m < 4; ++m) imma(C[m], Ar[m][0], B0);
            #pragma unroll
            for (int m = 0; m < 4; ++m) imma(C[m], Ar[m][1], B1);
            #pragma unroll
            for (int m = 0; m < 4; ++m) {
                float s0 = fmaf(sf2[m][0], (float)C[m][0], eqA);
                float s1 = fmaf(sf2[m][0], (float)C[m][1], eqB);
                float s2 = fmaf(sf2[m][1], (float)C[m][2], eqA);
                float s3 = fmaf(sf2[m][1], (float)C[m][3], eqB);
                minv[2 * m]     = fminf(minv[2 * m], fminf(s0, s1));
                minv[2 * m + 1] = fminf(minv[2 * m + 1], fminf(s2, s3));
                if (enq) {
                    int tlo = m * 16 + gr, thi = tlo + 8;
                    if (s0 <= thrv[2 * m]) {
                        unsigned p = atomicAdd(qc, 1u);
                        if (p < QCAP) qu[p] = ((unsigned)tlo << 16) | (unsigned)col; else qc[1] = 1;
                    }
                    if (s1 <= thrv[2 * m]) {
                        unsigned p = atomicAdd(qc, 1u);
                        if (p < QCAP) qu[p] = ((unsigned)tlo << 16) | (unsigned)(col + 1); else qc[1] = 1;
                    }
                    if (s2 <= thrv[2 * m + 1]) {
                        unsigned p = atomicAdd(qc, 1u);
                        if (p < QCAP) qu[p] = ((unsigned)thi << 16) | (unsigned)col; else qc[1] = 1;
                    }
                    if (s3 <= thrv[2 * m + 1]) {
                        unsigned p = atomicAdd(qc, 1u);
                        if (p < QCAP) qu[p] = ((unsigned)thi << 16) | (unsigned)(col + 1); else qc[1] = 1;
                    }
                }
            }
        }
    };
    auto minred = [&]() {
        #pragma unroll
        for (int i = 0; i < 8; ++i) {
            float m = minv[i];
            m = fminf(m, __shfl_xor_sync(~0u, m, 1));
            m = fminf(m, __shfl_xor_sync(~0u, m, 2));
            if (tig == 0) {
                int tt = (i >> 1) * 16 + gr + (i & 1) * 8;
                unsigned u = __float_as_uint(m);
                u = ((int)u < 0) ? ~u : (u | 0x80000000u);
                atomicMin(&smn[tt], u);
            }
        }
    };

    // pre-pass: chunk 0, min only
    pass(sB, 0, false);
    minred();
    __syncthreads();

    // main passes with live thresholds
    #pragma unroll 1
    for (int c = 0; c < 4; ++c) {
        if (c == 1 || c == 2) asm volatile("cp.async.wait_group 1;");
        if (c == 3)           asm volatile("cp.async.wait_group 0;");
        __syncthreads();
        #pragma unroll
        for (int i = 0; i < 8; ++i) {
            int tt = (i >> 1) * 16 + gr + (i & 1) * 8;
            thrv[i] = unmap(smn[tt]) + sdl[tt];
        }
        pass(sB + (c & 1) * 20480, c * 256, true);
        minred();
        __syncthreads();
        if (c < 2) {
            int src = (c + 2) * 256;
            for (int i = tid; i < 1024; i += 256) {
                int code = i >> 2, seg = i & 3;
                asm volatile("cp.async.cg.shared.global [%0], [%1], 16;"
                    :: "r"(sBsh + (c & 1) * 20480 + code * 80 + seg * 16),
                       "l"(cbq + (size_t)(src + code) * 64 + seg * 16));
            }
            asm volatile("cp.async.commit_group;");
        }
    }
    __syncthreads();

    // exact rescore of candidates
    if (!qc[1]) {
        unsigned n = min(qc[0], (unsigned)QCAP);
        for (unsigned i = tid; i < n; i += 256) {
            unsigned e = qu[i];
            int tt = (int)(e >> 16), k = (int)(e & 0xffffu);
            float s = exact_score((const float4*)(z + (size_t)(tb + tt) * 64),
                                  (const float4*)(cb + (size_t)k * 64), szq[tt], seq[k]);
            atomicMin(&cand[tt], packkey(s, k));
        }
    } else {   // overflow: full exact scan
        int tt = tid >> 2, kb = (tid & 3) * 256;
        unsigned long long best = ~0ULL;
        for (int k = kb; k < kb + 256; ++k) {
            float s = exact_score((const float4*)(z + (size_t)(tb + tt) * 64),
                                  (const float4*)(cb + (size_t)k * 64), szq[tt], seq[k]);
            unsigned long long p = packkey(s, k);
            if (p < best) best = p;
        }
        atomicMin(&cand[tt], best);
    }
    __syncthreads();

    // outputs: index, STE, MSE partial, hist
    {
        int idx = (int)(unsigned)cand[t];
        if (q == 0) {
            out[(size_t)NT * 64 + tb + t] = (float)idx;
            atomicAdd(&g_hist[idx], 1);
        }
        const float4* cp = (const float4*)(cb + (size_t)idx * 64 + q * 16);
        float* op = out + (size_t)(tb + t) * 64 + q * 16;
        double acc = 0.0;
        #pragma unroll
        for (int j = 0; j < 4; ++j) {
            float4 e = cp[j], v = zr[j];
            float dx = e.x - v.x, dy = e.y - v.y, dz = e.z - v.z, dw = e.w - v.w;
            *(float4*)(op + j * 4) = make_float4(v.x + dx, v.y + dy, v.z + dz, v.w + dw);
            acc += (double)(dx * dx) + (double)(dy * dy) + (double)(dz * dz) + (double)(dw * dw);
        }
        srd[tid] = acc;
    }
    __syncthreads();
    #pragma unroll
    for (int o = 128; o; o >>= 1) {
        if (tid < o) srd[tid] += srd[tid + o];
        __syncthreads();
    }
    if (tid == 0) g_partial[blockIdx.x] = srd[0];
}

// ---------------- final ----------------
__global__ void __launch_bounds__(1024) vq_final(float* __restrict__ out)
{
    __shared__ double sr[1024];
    __shared__ double sl;
    const int tid = threadIdx.x;
    sr[tid] = g_partial[tid] + g_partial[tid + 1024];
    __syncthreads();
    #pragma unroll
    for (int o = 512; o; o >>= 1) {
        if (tid < o) sr[tid] += sr[tid + o];
        __syncthreads();
    }
    if (tid == 0) sl = sr[0];
    __syncthreads();
    {
        float p = (float)g_hist[tid] / 131072.0f + 1e-10f;
        sr[tid] = (double)(p * logf(p));
    }
    __syncthreads();
    #pragma unroll
    for (int o = 512; o; o >>= 1) {
        if (tid < o) sr[tid] += sr[tid + o];
        __syncthreads();
    }
    if (tid == 0) {
        const size_t b = (size_t)NT * 64 + NT;
        float cl = (float)(sl / (double)((size_t)NT * 64));
        float en = (float)(-sr[0]);
        out[b + 0] = cl;
        out[b + 1] = 0.25f * cl;
        out[b + 2] = -0.1f * (en / 6.9314718055994531f);
        out[b + 3] = expf(en);
    }
}

extern "C" void kernel_launch(void* const* d_in, const int* in_sizes, int n_in,
                              void* d_out, int out_size)
{
    const float* z  = (const float*)d_in[0];
    const float* cb = (const float*)d_in[1];
    float* out = (float*)d_out;
    static bool done = false;
    if (!done) {
        cudaFuncSetAttribute(vq_main, cudaFuncAttributeMaxDynamicSharedMemorySize, SMEMSZ);
        done = true;
    }
    vq_prep<<<128, 256>>>(cb);
    vq_quant<<<64, 256>>>(cb);
    vq_main<<<NBLK, 256, SMEMSZ>>>(z, cb, out);
    vq_final<<<1, 1024>>>(out);
}

// round 10
// speedup vs baseline: 2.3978x; 1.0534x over previous
#include <cuda_runtime.h>
#include <cuda_fp16.h>
#include <cstdint>

#define NT 131072
#define NCODE 1024
#define TOKB 64
#define NBLK (NT / TOKB)
#define QCAP 768

__device__ float  g_esq[NCODE];
__device__ float  g_emaxb[128];
__device__ int    g_s8b[64];
__device__ int    g_hist[NCODE];
__device__ double g_partial[NBLK];
__device__ unsigned g_done;
__device__ unsigned g_cbq[NCODE * 16];   // s8-packed codebook rows (64 B/code)

// ---- smem byte offsets ----
#define O_A    0        // s8 [64][80]              5120
#define O_B    5120     // s8 [2][256][80]          40960
#define O_SC0  46080    // half[64][264]            33792  (chunk-0 scores)
#define O_EQ   79872    // float[1024]              4096
#define O_ZQ   83968    // float[64]
#define O_DL   84224    // float[64]
#define O_SF   84480    // float[64]
#define O_ISZ  84736    // float[64]
#define O_MN   84992    // uint [64]
#define O_CD   85248    // u64  [64]
#define O_QU   85760    // u32  [768]
#define O_QC   88832    // u32 x2
#define O_P    88840    // float[3][256]
#define O_RD   91912    // double[256]
#define SMEMSZ 93960

static __device__ __forceinline__ void imma(int* c, const unsigned* a, const unsigned* b) {
    asm volatile("mma.sync.aligned.m16n8k32.row.col.s32.s8.s8.s32 "
        "{%0,%1,%2,%3},{%4,%5,%6,%7},{%8,%9},{%0,%1,%2,%3};"
        : "+r"(c[0]), "+r"(c[1]), "+r"(c[2]), "+r"(c[3])
        : "r"(a[0]), "r"(a[1]), "r"(a[2]), "r"(a[3]), "r"(b[0]), "r"(b[1]));
}
static __device__ __forceinline__ unsigned long long packkey(float s, int k) {
    unsigned u = __float_as_uint(s);
    u = ((int)u < 0) ? ~u : (u | 0x80000000u);
    return ((unsigned long long)u << 32) | (unsigned)k;
}
static __device__ __forceinline__ float unmap(unsigned u) {
    return __uint_as_float((u & 0x80000000u) ? (u & 0x7FFFFFFFu) : ~u);
}
static __device__ __forceinline__ float exact_score(const float4* zr, const float4* cr,
                                                    float zsq, float esq) {
    float dot = 0.f;
    #pragma unroll
    for (int m = 0; m < 16; ++m) {
        float4 a = zr[m], b = cr[m];
        dot = fmaf(a.x, b.x, dot); dot = fmaf(a.y, b.y, dot);
        dot = fmaf(a.z, b.z, dot); dot = fmaf(a.w, b.w, dot);
    }
    return fmaf(-2.f, dot, zsq) + esq;
}

// ---------------- prep1: esq, emax per block, zero hist ----------------
__global__ void __launch_bounds__(256) vq_prep(const float* __restrict__ cb)
{
    __shared__ float wm[8];
    int w = threadIdx.x >> 5, l = threadIdx.x & 31;
    int k = blockIdx.x * 8 + w;
    float2 v = ((const float2*)(cb + (size_t)k * 64))[l];
    float sq = fmaf(v.y, v.y, v.x * v.x);
    float am = fmaxf(fabsf(v.x), fabsf(v.y));
    #pragma unroll
    for (int o = 16; o; o >>= 1) {
        sq += __shfl_xor_sync(~0u, sq, o);
        am = fmaxf(am, __shfl_xor_sync(~0u, am, o));
    }
    if (l == 0) { g_esq[k] = sq; wm[w] = am; }
    __syncthreads();
    if (threadIdx.x == 0) {
        float m = wm[0];
        #pragma unroll
        for (int i = 1; i < 8; ++i) m = fmaxf(m, wm[i]);
        g_emaxb[blockIdx.x] = m;
    }
    if (threadIdx.x < 8) g_hist[blockIdx.x * 8 + threadIdx.x] = 0;
}

// ---------------- prep2: quantize codebook to s8, per-block S8 max ----------------
__global__ void __launch_bounds__(256) vq_quant(const float* __restrict__ cb)
{
    __shared__ float sm[128];
    __shared__ int scode[16];
    int tid = threadIdx.x;
    if (tid < 128) sm[tid] = g_emaxb[tid];
    __syncthreads();
    if (tid == 0) {
        float m = sm[0];
        for (int i = 1; i < 128; ++i) m = fmaxf(m, sm[i]);
        sm[0] = m;
    }
    __syncthreads();
    float inv_se = 127.f / sm[0];
    int code = blockIdx.x * 16 + (tid >> 4), q = tid & 15;
    float4 v = *(const float4*)(cb + (size_t)code * 64 + q * 4);
    int a = __float2int_rn(v.x * inv_se), b = __float2int_rn(v.y * inv_se);
    int c = __float2int_rn(v.z * inv_se), d = __float2int_rn(v.w * inv_se);
    g_cbq[code * 16 + q] = (a & 255) | ((b & 255) << 8) | ((c & 255) << 16) | ((d & 255) << 24);
    int s = abs(a) + abs(b) + abs(c) + abs(d);
    #pragma unroll
    for (int o = 8; o; o >>= 1) s += __shfl_down_sync(~0u, s, o, 16);
    if (q == 0) scode[tid >> 4] = s;
    __syncthreads();
    if (tid == 0) {
        int m = scode[0];
        #pragma unroll
        for (int i = 1; i < 16; ++i) m = max(m, scode[i]);
        g_s8b[blockIdx.x] = m;
    }
}

// ---------------- main ----------------
extern __shared__ unsigned char smraw[];

__global__ void __launch_bounds__(256, 2)
vq_main(const float* __restrict__ z, const float* __restrict__ cb, float* __restrict__ out)
{
    signed char* sA = (signed char*)(smraw + O_A);
    signed char* sB = (signed char*)(smraw + O_B);
    __half* sbuf = (__half*)(smraw + O_SC0);
    float* seq  = (float*)(smraw + O_EQ);
    float* szq  = (float*)(smraw + O_ZQ);
    float* sdl  = (float*)(smraw + O_DL);
    float* ssf  = (float*)(smraw + O_SF);
    float* sisz = (float*)(smraw + O_ISZ);
    unsigned* smn = (unsigned*)(smraw + O_MN);
    unsigned long long* cand = (unsigned long long*)(smraw + O_CD);
    unsigned* qu = (unsigned*)(smraw + O_QU);
    unsigned* qc = (unsigned*)(smraw + O_QC);
    float* psq = (float*)(smraw + O_P);
    float* pab = psq + 256;
    float* pmx = psq + 512;
    double* srd = (double*)(smraw + O_RD);

    const int tid = threadIdx.x, w = tid >> 5, l = tid & 31;
    const int tb = blockIdx.x * TOKB;
    const int gr = l >> 2, tig = l & 3;
    const unsigned sBsh = (unsigned)__cvta_generic_to_shared(sB);
    const char* cbq = (const char*)g_cbq;

    // prefetch B chunks 0,1 (s8, 64 B/code -> stride 80)
    #pragma unroll
    for (int cc = 0; cc < 2; ++cc) {
        for (int i = tid; i < 1024; i += 256) {
            int code = i >> 2, seg = i & 3;
            asm volatile("cp.async.cg.shared.global [%0], [%1], 16;"
                :: "r"(sBsh + cc * 20480 + code * 80 + seg * 16),
                   "l"(cbq + (size_t)(cc * 256 + code) * 64 + seg * 16));
        }
        asm volatile("cp.async.commit_group;");
    }

    // z tile in regs + partial stats
    const int t = tid >> 2, q = tid & 3;
    float4 zr[4];
    {
        const float4* zp = (const float4*)(z + (size_t)(tb + t) * 64 + q * 16);
        float ps = 0.f, pa = 0.f, pm = 0.f;
        #pragma unroll
        for (int j = 0; j < 4; ++j) {
            float4 v = zp[j]; zr[j] = v;
            ps = fmaf(v.x, v.x, ps); ps = fmaf(v.y, v.y, ps);
            ps = fmaf(v.z, v.z, ps); ps = fmaf(v.w, v.w, ps);
            pa += fabsf(v.x) + fabsf(v.y) + fabsf(v.z) + fabsf(v.w);
            pm = fmaxf(pm, fmaxf(fmaxf(fabsf(v.x), fabsf(v.y)), fmaxf(fabsf(v.z), fabsf(v.w))));
        }
        psq[tid] = ps; pab[tid] = pa; pmx[tid] = pm;
    }
    if (tid < 128) ((float*)qu)[tid] = g_emaxb[tid];
    if (tid < 64) { ((int*)qu)[128 + tid] = g_s8b[tid]; smn[tid] = 0xFFFFFFFFu; cand[tid] = ~0ULL; }
    if (tid == 0) { qc[0] = 0; qc[1] = 0; }
    for (int i = tid; i < NCODE; i += 256) seq[i] = g_esq[i];
    __syncthreads();

    if (tid < 64) {
        float em = ((float*)qu)[0];
        #pragma unroll
        for (int i = 1; i < 128; ++i) em = fmaxf(em, ((float*)qu)[i]);
        int S8 = ((int*)qu)[128];
        #pragma unroll
        for (int i = 1; i < 64; ++i) S8 = max(S8, ((int*)qu)[128 + i]);
        float zq_ = psq[tid * 4] + psq[tid * 4 + 1] + psq[tid * 4 + 2] + psq[tid * 4 + 3];
        float ab  = pab[tid * 4] + pab[tid * 4 + 1] + pab[tid * 4 + 2] + pab[tid * 4 + 3];
        float mx  = fmaxf(fmaxf(pmx[tid * 4], pmx[tid * 4 + 1]), fmaxf(pmx[tid * 4 + 2], pmx[tid * 4 + 3]));
        float se = em * (1.f / 127.f);
        float zm = fmaxf(mx, 1e-30f);
        float sz = zm * (1.f / 127.f);
        szq[tid] = zq_;
        ssf[tid] = -2.f * se * sz;
        sdl[tid] = se * (ab + sz * (float)S8) + 1e-4f;
        sisz[tid] = 127.f / zm;
    }
    __syncthreads();

    {   // quantize A into smem s8 (stride 80)
        float isz = sisz[t];
        #pragma unroll
        for (int j = 0; j < 4; ++j) {
            float4 v = zr[j];
            int a = __float2int_rn(v.x * isz), b = __float2int_rn(v.y * isz);
            int c = __float2int_rn(v.z * isz), d = __float2int_rn(v.w * isz);
            *(unsigned*)(sA + t * 80 + q * 16 + j * 4) =
                (a & 255) | ((b & 255) << 8) | ((c & 255) << 16) | ((d & 255) << 24);
        }
    }
    asm volatile("cp.async.wait_group 1;");
    __syncthreads();

    // A fragments
    unsigned Ar[4][2][4];
    #pragma unroll
    for (int m = 0; m < 4; ++m)
        #pragma unroll
        for (int kh = 0; kh < 2; ++kh) {
            int base = (m * 16 + gr) * 80 + tig * 4 + kh * 32;
            Ar[m][kh][0] = *(const unsigned*)(sA + base);
            Ar[m][kh][1] = *(const unsigned*)(sA + base + 640);
            Ar[m][kh][2] = *(const unsigned*)(sA + base + 16);
            Ar[m][kh][3] = *(const unsigned*)(sA + base + 656);
        }
    float sf2[4][2];
    #pragma unroll
    for (int m = 0; m < 4; ++m) {
        sf2[m][0] = ssf[m * 16 + gr];
        sf2[m][1] = ssf[m * 16 + gr + 8];
    }
    float minv[8];
    #pragma unroll
    for (int i = 0; i < 8; ++i) minv[i] = 3.4e38f;
    float thrv[8];
    #pragma unroll
    for (int i = 0; i < 8; ++i) thrv[i] = 0.f;

    auto pass = [&](const signed char* bb, int cbase, bool enq, bool store) {
        #pragma unroll
        for (int j = 0; j < 4; ++j) {
            int crow = (w * 32 + j * 8 + gr) * 80 + tig * 4;
            unsigned B0[2], B1[2];
            B0[0] = *(const unsigned*)(bb + crow);
            B0[1] = *(const unsigned*)(bb + crow + 16);
            B1[0] = *(const unsigned*)(bb + crow + 32);
            B1[1] = *(const unsigned*)(bb + crow + 48);
            int col = cbase + w * 32 + j * 8 + tig * 2;
            float eqA = seq[col], eqB = seq[col + 1];
            int C[4][4];
            #pragma unroll
            for (int m = 0; m < 4; ++m) { C[m][0] = 0; C[m][1] = 0; C[m][2] = 0; C[m][3] = 0; }
            #pragma unroll
            for (int m = 0; m < 4; ++m) imma(C[m], Ar[m][0], B0);
            #pragma unroll
            for (int m = 0; m < 4; ++m) imma(C[m], Ar[m][1], B1);
            #pragma unroll
            for (int m = 0; m < 4; ++m) {
                float s0 = fmaf(sf2[m][0], (float)C[m][0], eqA);
                float s1 = fmaf(sf2[m][0], (float)C[m][1], eqB);
                float s2 = fmaf(sf2[m][1], (float)C[m][2], eqA);
                float s3 = fmaf(sf2[m][1], (float)C[m][3], eqB);
                minv[2 * m]     = fminf(minv[2 * m], fminf(s0, s1));
                minv[2 * m + 1] = fminf(minv[2 * m + 1], fminf(s2, s3));
                int tlo = m * 16 + gr, thi = tlo + 8;
                if (store) {
                    int lc = col - cbase;
                    *(__half2*)(sbuf + tlo * 264 + lc) = __floats2half2_rn(s0, s1);
                    *(__half2*)(sbuf + thi * 264 + lc) = __floats2half2_rn(s2, s3);
                }
                if (enq) {
                    if (s0 <= thrv[2 * m]) {
                        unsigned p = atomicAdd(qc, 1u);
                        if (p < QCAP) qu[p] = ((unsigned)tlo << 16) | (unsigned)col; else qc[1] = 1;
                    }
                    if (s1 <= thrv[2 * m]) {
                        unsigned p = atomicAdd(qc, 1u);
                        if (p < QCAP) qu[p] = ((unsigned)tlo << 16) | (unsigned)(col + 1); else qc[1] = 1;
                    }
                    if (s2 <= thrv[2 * m + 1]) {
                        unsigned p = atomicAdd(qc, 1u);
                        if (p < QCAP) qu[p] = ((unsigned)thi << 16) | (unsigned)col; else qc[1] = 1;
                    }
                    if (s3 <= thrv[2 * m + 1]) {
                        unsigned p = atomicAdd(qc, 1u);
                        if (p < QCAP) qu[p] = ((unsigned)thi << 16) | (unsigned)(col + 1); else qc[1] = 1;
                    }
                }
            }
        }
    };
    auto minred = [&]() {
        #pragma unroll
        for (int i = 0; i < 8; ++i) {
            float m = minv[i];
            m = fminf(m, __shfl_xor_sync(~0u, m, 1));
            m = fminf(m, __shfl_xor_sync(~0u, m, 2));
            if (tig == 0) {
                int tt = (i >> 1) * 16 + gr + (i & 1) * 8;
                unsigned u = __float_as_uint(m);
                u = ((int)u < 0) ? ~u : (u | 0x80000000u);
                atomicMin(&smn[tt], u);
            }
        }
    };

    // pre-pass: chunk 0, store scores + min (no recompute later)
    pass(sB, 0, false, true);
    minred();
    __syncthreads();

    // chunk-0 slot free -> prefetch chunk 2 into slot 0
    for (int i = tid; i < 1024; i += 256) {
        int code = i >> 2, seg = i & 3;
        asm volatile("cp.async.cg.shared.global [%0], [%1], 16;"
            :: "r"(sBsh + code * 80 + seg * 16),
               "l"(cbq + (size_t)(512 + code) * 64 + seg * 16));
    }
    asm volatile("cp.async.commit_group;");

    // chunk-0 candidate scan from buffer (overlaps chunk-2 cp.async)
    #pragma unroll 1
    for (int r = 0; r < 8; ++r) {
        int tt = w * 8 + r;
        float thr = unmap(smn[tt]) + sdl[tt];
        uint4 v = *(const uint4*)(sbuf + tt * 264 + l * 8);
        const __half* h = (const __half*)&v;
        #pragma unroll
        for (int p = 0; p < 8; ++p)
            if (__half2float(h[p]) <= thr) {
                unsigned pos = atomicAdd(qc, 1u);
                if (pos < QCAP) qu[pos] = ((unsigned)tt << 16) | (unsigned)(l * 8 + p); else qc[1] = 1;
            }
    }

    // main chunks 1..3
    #pragma unroll 1
    for (int c = 1; c <= 3; ++c) {
        if (c < 3) asm volatile("cp.async.wait_group 1;");
        else       asm volatile("cp.async.wait_group 0;");
        __syncthreads();
        #pragma unroll
        for (int i = 0; i < 8; ++i) {
            int tt = (i >> 1) * 16 + gr + (i & 1) * 8;
            thrv[i] = unmap(smn[tt]) + sdl[tt];
        }
        pass(sB + (c & 1) * 20480, c * 256, true, false);
        if (c < 3) {
            minred();
            __syncthreads();
            if (c == 1) {   // chunk 3 into slot 1 (just consumed)
                for (int i = tid; i < 1024; i += 256) {
                    int code = i >> 2, seg = i & 3;
                    asm volatile("cp.async.cg.shared.global [%0], [%1], 16;"
                        :: "r"(sBsh + 20480 + code * 80 + seg * 16),
                           "l"(cbq + (size_t)(768 + code) * 64 + seg * 16));
                }
                asm volatile("cp.async.commit_group;");
            }
        }
    }
    __syncthreads();

    // exact rescore of candidates
    if (!qc[1]) {
        unsigned n = min(qc[0], (unsigned)QCAP);
        for (unsigned i = tid; i < n; i += 256) {
            unsigned e = qu[i];
            int tt = (int)(e >> 16), k = (int)(e & 0xffffu);
            float s = exact_score((const float4*)(z + (size_t)(tb + tt) * 64),
                                  (const float4*)(cb + (size_t)k * 64), szq[tt], seq[k]);
            atomicMin(&cand[tt], packkey(s, k));
        }
    } else {
        int tt = tid >> 2, kb = (tid & 3) * 256;
        unsigned long long best = ~0ULL;
        for (int k = kb; k < kb + 256; ++k) {
            float s = exact_score((const float4*)(z + (size_t)(tb + tt) * 64),
                                  (const float4*)(cb + (size_t)k * 64), szq[tt], seq[k]);
            unsigned long long p = packkey(s, k);
            if (p < best) best = p;
        }
        atomicMin(&cand[tt], best);
    }
    __syncthreads();

    // outputs: index, STE, MSE partial, hist
    {
        int idx = (int)(unsigned)cand[t];
        if (q == 0) {
            out[(size_t)NT * 64 + tb + t] = (float)idx;
            atomicAdd(&g_hist[idx], 1);
        }
        const float4* cp = (const float4*)(cb + (size_t)idx * 64 + q * 16);
        float* op = out + (size_t)(tb + t) * 64 + q * 16;
        double acc = 0.0;
        #pragma unroll
        for (int j = 0; j < 4; ++j) {
            float4 e = cp[j], v = zr[j];
            float dx = e.x - v.x, dy = e.y - v.y, dz = e.z - v.z, dw = e.w - v.w;
            *(float4*)(op + j * 4) = make_float4(v.x + dx, v.y + dy, v.z + dz, v.w + dw);
            acc += (double)(dx * dx) + (double)(dy * dy) + (double)(dz * dz) + (double)(dw * dw);
        }
        srd[tid] = acc;
    }
    __syncthreads();
    #pragma unroll
    for (int o = 128; o; o >>= 1) {
        if (tid < o) srd[tid] += srd[tid + o];
        __syncthreads();
    }
    if (tid == 0) g_partial[blockIdx.x] = srd[0];

    // ---- fused finalization: last block reduces everything ----
    __threadfence();
    __shared__ unsigned lastblk;
    if (tid == 0) lastblk = (atomicAdd(&g_done, 1u) == (unsigned)(NBLK - 1)) ? 1u : 0u;
    __syncthreads();
    if (!lastblk) return;

    double acc = 0.0;
    for (int i = tid; i < NBLK; i += 256) acc += g_partial[i];
    srd[tid] = acc;
    __syncthreads();
    #pragma unroll
    for (int o = 128; o; o >>= 1) {
        if (tid < o) srd[tid] += srd[tid + o];
        __syncthreads();
    }
    double sl = srd[0];
    __syncthreads();

    double ent = 0.0;
    for (int i = tid; i < NCODE; i += 256) {
        float p = (float)g_hist[i] / 131072.0f + 1e-10f;
        ent += (double)(p * logf(p));
    }
    srd[tid] = ent;
    __syncthreads();
    #pragma unroll
    for (int o = 128; o; o >>= 1) {
        if (tid < o) srd[tid] += srd[tid + o];
        __syncthreads();
    }
    if (tid == 0) {
        const size_t b = (size_t)NT * 64 + NT;
        float cl = (float)(sl / (double)((size_t)NT * 64));
        float en = (float)(-srd[0]);
        out[b + 0] = cl;
        out[b + 1] = 0.25f * cl;
        out[b + 2] = -0.1f * (en / 6.9314718055994531f);
        out[b + 3] = expf(en);
        g_done = 0;   // reset for next graph replay
    }
}

extern "C" void kernel_launch(void* const* d_in, const int* in_sizes, int n_in,
                              void* d_out, int out_size)
{
    const float* z  = (const float*)d_in[0];
    const float* cb = (const float*)d_in[1];
    float* out = (float*)d_out;
    static bool done = false;
    if (!done) {
        cudaFuncSetAttribute(vq_main, cudaFuncAttributeMaxDynamicSharedMemorySize, SMEMSZ);
        done = true;
    }
    vq_prep<<<128, 256>>>(cb);
    vq_quant<<<64, 256>>>(cb);
    vq_main<<<NBLK, 256, SMEMSZ>>>(z, cb, out);
}